// round 4
// baseline (speedup 1.0000x reference)
#include <cuda_runtime.h>
#include <cstdint>

// Input:  x  (4, 64, 512, 512) fp32  -> flatten (BC=256, 512, 512)
// Output: [ll | lh | hl | hh], each (256, 256, 256) fp32, concatenated.
//
// R4: smem-staged writes. Each block handles 8 input rows (4 row-pairs x 512
// cols) of one bc slice. Compute phase writes results into a 16KB smem buffer
// (4 planes x 4 rows x 256 floats); drain phase writes each plane as one
// block-wide contiguous 4KB burst. Goal: longer DRAM write bursts, fewer
// read/write stream interleavings.

static constexpr int BC    = 256;
static constexpr int H_OUT = 256;
static constexpr int W_OUT = 256;
static constexpr int PLANE = BC * H_OUT * W_OUT;   // 16,777,216 floats per plane
static constexpr int W4    = 128;                  // float4 per input row (512/4)
static constexpr int RP_PER_BLOCK = 4;             // row-pairs per block
static constexpr int THREADS = 256;

__device__ __forceinline__ float4 ldcs4(const float4* p) {
    float4 v;
    asm volatile("ld.global.cs.v4.f32 {%0,%1,%2,%3}, [%4];"
                 : "=f"(v.x), "=f"(v.y), "=f"(v.z), "=f"(v.w) : "l"(p));
    return v;
}

__device__ __forceinline__ void stcs4(float* p, float4 v) {
    asm volatile("st.global.cs.v4.f32 [%0], {%1,%2,%3,%4};"
                 :: "l"(p), "f"(v.x), "f"(v.y), "f"(v.z), "f"(v.w) : "memory");
}

__global__ void __launch_bounds__(THREADS) fast_dwt_kernel(
    const float4* __restrict__ x,
    float* __restrict__ out)
{
    __shared__ float s[4][RP_PER_BLOCK * W_OUT];   // 4 planes x 1024 floats = 16KB

    const unsigned tid = threadIdx.x;
    // Block -> (bc, ho_base): 64 blocks per bc (256 ho / 4 per block)
    const unsigned bid = blockIdx.x;
    const unsigned bc = bid >> 6;                 // / 64
    const unsigned ho_base = (bid & 63u) * RP_PER_BLOCK;

    // ---- compute phase: 512 patch units (4 row-pairs x 128 quads), 2/thread
    #pragma unroll
    for (int k = 0; k < 2; k++) {
        unsigned item = tid + k * THREADS;        // 0..511
        unsigned rp = item >> 7;                  // row-pair in tile, 0..3
        unsigned wq = item & 127u;                // quad in row, 0..127

        unsigned ho = ho_base + rp;
        unsigned row0 = (bc * 512u + 2u * ho) * W4;
        float4 r0 = ldcs4(x + row0 + wq);
        float4 r1 = ldcs4(x + row0 + W4 + wq);

        float2 ll, lh, hl, hh;
        {
            float apb = r0.x + r0.y, amb = r0.x - r0.y;
            float cpd = r1.x + r1.y, cmd = r1.x - r1.y;
            ll.x = (apb + cpd) * 0.5f;  lh.x = (apb - cpd) * 0.5f;
            hl.x = (amb + cmd) * 0.5f;  hh.x = (amb - cmd) * 0.5f;
        }
        {
            float apb = r0.z + r0.w, amb = r0.z - r0.w;
            float cpd = r1.z + r1.w, cmd = r1.z - r1.w;
            ll.y = (apb + cpd) * 0.5f;  lh.y = (apb - cpd) * 0.5f;
            hl.y = (amb + cmd) * 0.5f;  hh.y = (amb - cmd) * 0.5f;
        }

        unsigned so = rp * W_OUT + 2u * wq;       // offset in plane tile
        *(float2*)&s[0][so] = ll;
        *(float2*)&s[1][so] = lh;
        *(float2*)&s[2][so] = hl;
        *(float2*)&s[3][so] = hh;
    }

    __syncthreads();

    // ---- drain phase: each plane tile = 1024 floats = 256 float4, one/thread
    // Global base: plane p, rows ho_base..ho_base+3 of slice bc (contiguous)
    unsigned gbase = (bc * H_OUT + ho_base) * W_OUT;   // floats
    #pragma unroll
    for (int p = 0; p < 4; p++) {
        float4 v = *(float4*)&s[p][4u * tid];
        stcs4(out + (long long)p * PLANE + gbase + 4u * tid, v);
    }
}

extern "C" void kernel_launch(void* const* d_in, const int* in_sizes, int n_in,
                              void* d_out, int out_size)
{
    const float4* x = (const float4*)d_in[0];
    float* out = (float*)d_out;

    const int blocks = BC * (H_OUT / RP_PER_BLOCK);   // 256 * 64 = 16384
    fast_dwt_kernel<<<blocks, THREADS>>>(x, out);
}